// round 1
// baseline (speedup 1.0000x reference)
#include <cuda_runtime.h>

#define NMAX 100000
#define EMAX 3200000
#define NG 64
#define NC 10

// ---------------- device scratch (no allocations allowed) ----------------
__device__ int   gcn_is64;
__device__ __align__(16) int gcn_srcs[EMAX];
__device__ __align__(16) int gcn_dsts[EMAX];
__device__ int   gcn_batch[NMAX];
__device__ float gcn_deg[NMAX];
__device__ float gcn_dinv[NMAX];
__device__ float4 gcn_vals[NMAX * 2];   // g[i] padded to 8 floats
__device__ float4 gcn_acc[NMAX * 2];    // accumulator, padded to 8 floats
__device__ float gcn_pool[NG * NC];
__device__ float gcn_cnt[NG];

// vector reduction to global (sm_90+): one instruction covers 4 floats
__device__ __forceinline__ void red4(float4* p, float4 v) {
    asm volatile("red.global.add.v4.f32 [%0], {%1,%2,%3,%4};"
                 :: "l"(p), "f"(v.x), "f"(v.y), "f"(v.z), "f"(v.w)
                 : "memory");
}

// ---------------- init ----------------
__global__ __launch_bounds__(256) void k_init(int N) {
    int i = blockIdx.x * 256 + threadIdx.x;
    if (i < N) gcn_deg[i] = 1.0f;           // self-loop contributes 1 to degree
    if (i < NG) gcn_cnt[i] = 0.0f;
    if (i < NG * NC) gcn_pool[i] = 0.0f;
}

// ---------------- dtype detection: int32 vs int64 indices ----------------
__global__ void k_detect(const void* edge, int N) {
    const long long* p = (const long long*)edge;
    int bad = 0;
    for (int t = threadIdx.x; t < 128; t += 32) {
        long long v = p[t];
        if (v < 0 || v >= (long long)N) bad = 1;   // int32 data read as int64 -> huge values
    }
    bad = __any_sync(0xffffffffu, bad);
    if (threadIdx.x == 0) gcn_is64 = bad ? 0 : 1;
}

// ---------------- convert indices to int32 + degree + graph counts ----------------
__global__ __launch_bounds__(256) void k_convert(const void* edge, const void* batchp,
                                                 int N, int E) {
    int i = blockIdx.x * 256 + threadIdx.x;
    int is64 = gcn_is64;
    if (i < E) {
        int s, d;
        if (is64) {
            s = (int)((const long long*)edge)[i];
            d = (int)((const long long*)edge)[(size_t)E + i];
        } else {
            s = ((const int*)edge)[i];
            d = ((const int*)edge)[(size_t)E + i];
        }
        gcn_srcs[i] = s;
        gcn_dsts[i] = d;
        atomicAdd(&gcn_deg[d], 1.0f);
    }
    if (i < N) {
        int b = is64 ? (int)((const long long*)batchp)[i] : ((const int*)batchp)[i];
        gcn_batch[i] = b;
        atomicAdd(&gcn_cnt[b], 1.0f);
    }
}

// ---------------- layer-1 transform: g = (x @ W1) * dinv ----------------
__global__ __launch_bounds__(256) void k_mm1(const float* __restrict__ x,
                                             const float* __restrict__ W, int N) {
    __shared__ float sW[128 * 8];
    for (int t = threadIdx.x; t < 1024; t += 256) {
        int k = t >> 3, j = t & 7;
        sW[t] = (j < 6) ? W[k * 6 + j] : 0.0f;
    }
    __syncthreads();
    int i = blockIdx.x * 256 + threadIdx.x;
    if (i >= N) return;
    const float4* xr = (const float4*)(x + (size_t)i * 128);
    float a[6];
#pragma unroll
    for (int j = 0; j < 6; j++) a[j] = 0.0f;
#pragma unroll 8
    for (int k4 = 0; k4 < 32; k4++) {
        float4 xv = xr[k4];
        const float* wp = &sW[k4 * 32];
#pragma unroll
        for (int j = 0; j < 6; j++) {
            a[j] += xv.x * wp[j] + xv.y * wp[8 + j] + xv.z * wp[16 + j] + xv.w * wp[24 + j];
        }
    }
    float dinv = rsqrtf(gcn_deg[i]);
    gcn_dinv[i] = dinv;
    float4 v0 = make_float4(a[0] * dinv, a[1] * dinv, a[2] * dinv, a[3] * dinv);
    float4 v1 = make_float4(a[4] * dinv, a[5] * dinv, 0.0f, 0.0f);
    gcn_vals[2 * i] = v0; gcn_vals[2 * i + 1] = v1;   // self-loop term pre-seeded
    gcn_acc[2 * i]  = v0; gcn_acc[2 * i + 1]  = v1;
}

// ---------------- edge pass: acc[dst] += g[src] ----------------
__device__ __forceinline__ void edge_one(int s, int d) {
    float4 v0 = __ldg(&gcn_vals[2 * s]);
    float4 v1 = __ldg(&gcn_vals[2 * s + 1]);
    red4(&gcn_acc[2 * d], v0);
    red4(&gcn_acc[2 * d + 1], v1);
}

__global__ __launch_bounds__(256) void k_edge(int E) {
    int i = blockIdx.x * 256 + threadIdx.x;
    int e0 = i * 4;
    if (e0 + 3 < E) {
        int4 s4 = ((const int4*)gcn_srcs)[i];
        int4 d4 = ((const int4*)gcn_dsts)[i];
        edge_one(s4.x, d4.x);
        edge_one(s4.y, d4.y);
        edge_one(s4.z, d4.z);
        edge_one(s4.w, d4.w);
    } else if (e0 < E) {
        for (int e = e0; e < E; e++) edge_one(gcn_srcs[e], gcn_dsts[e]);
    }
}

// ---------------- fused finalize(prev layer) + transform(next layer) ----------------
// h = relu(dinv*acc + b_prev); g = APPLY_W ? (h @ W)*dinv : h*dinv ; acc = g
template <bool APPLY_W>
__global__ __launch_bounds__(256) void k_layer(const float* __restrict__ b,
                                               const float* __restrict__ W, int N) {
    __shared__ float sW[48];
    __shared__ float sb[6];
    if (threadIdx.x < 48) {
        int k = threadIdx.x >> 3, j = threadIdx.x & 7;
        float v = 0.0f;
        if (APPLY_W && j < 6) v = W[k * 6 + j];
        sW[threadIdx.x] = v;
    }
    if (threadIdx.x < 6) sb[threadIdx.x] = b[threadIdx.x];
    __syncthreads();
    int i = blockIdx.x * 256 + threadIdx.x;
    if (i >= N) return;
    float dinv = gcn_dinv[i];
    float4 A0 = gcn_acc[2 * i], A1 = gcn_acc[2 * i + 1];
    float h[6];
    h[0] = fmaxf(dinv * A0.x + sb[0], 0.0f);
    h[1] = fmaxf(dinv * A0.y + sb[1], 0.0f);
    h[2] = fmaxf(dinv * A0.z + sb[2], 0.0f);
    h[3] = fmaxf(dinv * A0.w + sb[3], 0.0f);
    h[4] = fmaxf(dinv * A1.x + sb[4], 0.0f);
    h[5] = fmaxf(dinv * A1.y + sb[5], 0.0f);
    float o[6];
    if (APPLY_W) {
#pragma unroll
        for (int j = 0; j < 6; j++) {
            float s = 0.0f;
#pragma unroll
            for (int k = 0; k < 6; k++) s += h[k] * sW[k * 8 + j];
            o[j] = s * dinv;
        }
    } else {
#pragma unroll
        for (int j = 0; j < 6; j++) o[j] = h[j] * dinv;
    }
    float4 v0 = make_float4(o[0], o[1], o[2], o[3]);
    float4 v1 = make_float4(o[4], o[5], 0.0f, 0.0f);
    gcn_vals[2 * i] = v0; gcn_vals[2 * i + 1] = v1;
    gcn_acc[2 * i]  = v0; gcn_acc[2 * i + 1]  = v1;
}

// ---------------- final layer epilogue + pooled sums ----------------
// node out = relu( (dinv*acc) @ Wf + bf ); pool[batch] += out (smem-staged, batch is sorted)
__global__ __launch_bounds__(256) void k_final(const float* __restrict__ Wf,
                                               const float* __restrict__ bf, int N) {
    __shared__ float sW[60];
    __shared__ float sb[10];
    __shared__ float sp[NG * NC];
    for (int t = threadIdx.x; t < NG * NC; t += 256) sp[t] = 0.0f;
    if (threadIdx.x < 60) sW[threadIdx.x] = Wf[threadIdx.x];
    if (threadIdx.x < 10) sb[threadIdx.x] = bf[threadIdx.x];
    __syncthreads();
    int i = blockIdx.x * 256 + threadIdx.x;
    if (i < N) {
        float dinv = gcn_dinv[i];
        float4 A0 = gcn_acc[2 * i], A1 = gcn_acc[2 * i + 1];
        float a[6] = { dinv * A0.x, dinv * A0.y, dinv * A0.z,
                       dinv * A0.w, dinv * A1.x, dinv * A1.y };
        int bg = gcn_batch[i];
#pragma unroll
        for (int c = 0; c < 10; c++) {
            float s = sb[c];
#pragma unroll
            for (int j = 0; j < 6; j++) s += a[j] * sW[j * 10 + c];
            s = fmaxf(s, 0.0f);
            atomicAdd(&sp[bg * 10 + c], s);
        }
    }
    __syncthreads();
    int first = blockIdx.x * 256;
    if (first >= N) return;
    int last = min(first + 255, N - 1);
    int bmin = gcn_batch[first], bmax = gcn_batch[last];   // batch sorted
    int cnt = (bmax - bmin + 1) * 10;
    for (int t = threadIdx.x; t < cnt; t += 256) {
        float v = sp[bmin * 10 + t];
        if (v != 0.0f) atomicAdd(&gcn_pool[bmin * 10 + t], v);
    }
}

// ---------------- mean + log_softmax ----------------
__global__ void k_out(float* __restrict__ out) {
    int g = threadIdx.x;
    if (g >= NG) return;
    float cnt = fmaxf(gcn_cnt[g], 1.0f);
    float p[10];
    float m = -1e30f;
#pragma unroll
    for (int c = 0; c < 10; c++) {
        p[c] = gcn_pool[g * 10 + c] / cnt;
        m = fmaxf(m, p[c]);
    }
    float s = 0.0f;
#pragma unroll
    for (int c = 0; c < 10; c++) s += expf(p[c] - m);
    float l = logf(s);
#pragma unroll
    for (int c = 0; c < 10; c++) out[g * 10 + c] = p[c] - m - l;
}

// ---------------- launch ----------------
extern "C" void kernel_launch(void* const* d_in, const int* in_sizes, int n_in,
                              void* d_out, int out_size) {
    const float* x     = (const float*)d_in[0];
    const void*  edge  = d_in[1];
    const void*  batch = d_in[2];
    const float* W1 = (const float*)d_in[3];
    const float* b1 = (const float*)d_in[4];
    const float* W2 = (const float*)d_in[5];
    const float* b2 = (const float*)d_in[6];
    const float* W3 = (const float*)d_in[7];
    const float* b3 = (const float*)d_in[8];
    const float* W4 = (const float*)d_in[9];
    const float* b4 = (const float*)d_in[10];
    const float* W5 = (const float*)d_in[11];
    const float* b5 = (const float*)d_in[12];
    const float* W6 = (const float*)d_in[13];
    const float* b6 = (const float*)d_in[14];
    const float* Wf = (const float*)d_in[15];
    const float* bf = (const float*)d_in[16];

    int N = in_sizes[0] / 128;
    int E = in_sizes[1] / 2;
    float* out = (float*)d_out;

    int nb_n = (N + 255) / 256;
    int nb_e = (E + 255) / 256;
    int nb_e4 = ((E + 3) / 4 + 255) / 256;

    k_init<<<nb_n, 256>>>(N);
    k_detect<<<1, 32>>>(edge, N);
    k_convert<<<nb_e, 256>>>(edge, batch, N, E);

    // layer 1
    k_mm1<<<nb_n, 256>>>(x, W1, N);
    k_edge<<<nb_e4, 256>>>(E);
    // layers 2..6
    k_layer<true><<<nb_n, 256>>>(b1, W2, N);
    k_edge<<<nb_e4, 256>>>(E);
    k_layer<true><<<nb_n, 256>>>(b2, W3, N);
    k_edge<<<nb_e4, 256>>>(E);
    k_layer<true><<<nb_n, 256>>>(b3, W4, N);
    k_edge<<<nb_e4, 256>>>(E);
    k_layer<true><<<nb_n, 256>>>(b4, W5, N);
    k_edge<<<nb_e4, 256>>>(E);
    k_layer<true><<<nb_n, 256>>>(b5, W6, N);
    k_edge<<<nb_e4, 256>>>(E);
    // layer 7 aggregation (aggregate-then-matmul: width 6 instead of 10)
    k_layer<false><<<nb_n, 256>>>(b6, nullptr, N);
    k_edge<<<nb_e4, 256>>>(E);
    // final matmul + relu + pooled sums
    k_final<<<nb_n, 256>>>(Wf, bf, N);
    // mean + log_softmax
    k_out<<<1, 64>>>(out);
}

// round 2
// speedup vs baseline: 1.1679x; 1.1679x over previous
#include <cuda_runtime.h>

#define NMAX 100000
#define EMAX 3200000
#define NG 64
#define NC 10
#define SCANB 1024

// ---------------- device scratch ----------------
__device__ int gcn_is64;
__device__ int gcn_degi[NMAX];          // in-degree (without self loop)
__device__ int gcn_off[NMAX + 1];       // CSR row offsets (by dst)
__device__ int gcn_cur[NMAX];           // fill cursors
__device__ int gcn_blocksum[128];
__device__ __align__(16) int gcn_csrc[EMAX];   // CSR column (src) indices
__device__ int gcn_batch[NMAX];
__device__ float gcn_dinv[NMAX];
__device__ __align__(16) float4 gcn_bufA[NMAX * 2];  // node values, 32B/node
__device__ __align__(16) float4 gcn_bufB[NMAX * 2];
__device__ float gcn_pool[NG * NC];
__device__ float gcn_cnt[NG];

// ---------------- init ----------------
__global__ __launch_bounds__(256) void k_init(int N) {
    int i = blockIdx.x * 256 + threadIdx.x;
    if (i < N) gcn_degi[i] = 0;
    if (i < NG) gcn_cnt[i] = 0.0f;
    if (i < NG * NC) gcn_pool[i] = 0.0f;
}

// ---------------- dtype detection: int32 vs int64 indices ----------------
__global__ void k_detect(const void* edge, int N) {
    const long long* p = (const long long*)edge;
    int bad = 0;
    for (int t = threadIdx.x; t < 128; t += 32) {
        long long v = p[t];
        if (v < 0 || v >= (long long)N) bad = 1;
    }
    bad = __any_sync(0xffffffffu, bad);
    if (threadIdx.x == 0) gcn_is64 = bad ? 0 : 1;
}

// ---------------- degree histogram + batch counts ----------------
__global__ __launch_bounds__(256) void k_hist(const void* edge, const void* batchp,
                                              int N, int E) {
    int i = blockIdx.x * 256 + threadIdx.x;
    int is64 = gcn_is64;
    if (i < E) {
        int d = is64 ? (int)((const long long*)edge)[(size_t)E + i]
                     : ((const int*)edge)[(size_t)E + i];
        atomicAdd(&gcn_degi[d], 1);
    }
    if (i < N) {
        int b = is64 ? (int)((const long long*)batchp)[i] : ((const int*)batchp)[i];
        gcn_batch[i] = b;
        atomicAdd(&gcn_cnt[b], 1.0f);
    }
}

// ---------------- 3-phase exclusive scan of degi -> off ----------------
__global__ __launch_bounds__(SCANB) void k_scan1(int N) {
    __shared__ int s[SCANB];
    int t = threadIdx.x;
    int i = blockIdx.x * SCANB + t;
    int v = (i < N) ? gcn_degi[i] : 0;
    s[t] = v;
    __syncthreads();
    for (int d = 1; d < SCANB; d <<= 1) {
        int x = (t >= d) ? s[t - d] : 0;
        __syncthreads();
        s[t] += x;
        __syncthreads();
    }
    if (i < N) gcn_off[i] = s[t] - v;   // exclusive (local)
    if (t == SCANB - 1) gcn_blocksum[blockIdx.x] = s[t];
}

__global__ void k_scan2(int nblk) {
    __shared__ int s[128];
    int t = threadIdx.x;
    int v = (t < nblk) ? gcn_blocksum[t] : 0;
    s[t] = v;
    __syncthreads();
    for (int d = 1; d < 128; d <<= 1) {
        int x = (t >= d) ? s[t - d] : 0;
        __syncthreads();
        s[t] += x;
        __syncthreads();
    }
    if (t < nblk) gcn_blocksum[t] = s[t] - v;  // exclusive block bases
}

__global__ __launch_bounds__(256) void k_scan3(int N, int E) {
    int i = blockIdx.x * 256 + threadIdx.x;
    if (i < N) {
        int o = gcn_off[i] + gcn_blocksum[i >> 10];
        gcn_off[i] = o;
        gcn_cur[i] = o;
    }
    if (i == 0) gcn_off[N] = E;
}

// ---------------- CSR fill (counting-sort edges by dst) ----------------
__global__ __launch_bounds__(256) void k_fill(const void* edge, int E) {
    int i = blockIdx.x * 256 + threadIdx.x;
    if (i >= E) return;
    int is64 = gcn_is64;
    int s, d;
    if (is64) {
        s = (int)((const long long*)edge)[i];
        d = (int)((const long long*)edge)[(size_t)E + i];
    } else {
        s = ((const int*)edge)[i];
        d = ((const int*)edge)[(size_t)E + i];
    }
    int pos = atomicAdd(&gcn_cur[d], 1);
    gcn_csrc[pos] = s;
}

// ---------------- layer-1 transform: bufA = (x @ W1) * dinv ----------------
// 4 threads per row, shfl-combined: 4x MLP + 4x occupancy vs 1 thread/row.
__global__ __launch_bounds__(256) void k_mm1(const float* __restrict__ x,
                                             const float* __restrict__ W, int N) {
    __shared__ float sW[128 * 8];
    for (int t = threadIdx.x; t < 1024; t += 256) {
        int k = t >> 3, j = t & 7;
        sW[t] = (j < 6) ? W[k * 6 + j] : 0.0f;
    }
    __syncthreads();
    int g = blockIdx.x * 256 + threadIdx.x;
    int i = g >> 2;
    int q = g & 3;
    if (i >= N) return;
    const float4* xr = (const float4*)(x + (size_t)i * 128) + q * 8;
    float a[6];
#pragma unroll
    for (int j = 0; j < 6; j++) a[j] = 0.0f;
#pragma unroll
    for (int k4 = 0; k4 < 8; k4++) {
        float4 xv = xr[k4];
        const float* wp = &sW[(q * 8 + k4) * 32];
#pragma unroll
        for (int j = 0; j < 6; j++) {
            a[j] += xv.x * wp[j] + xv.y * wp[8 + j] + xv.z * wp[16 + j] + xv.w * wp[24 + j];
        }
    }
#pragma unroll
    for (int j = 0; j < 6; j++) {
        a[j] += __shfl_xor_sync(0xffffffffu, a[j], 1);
        a[j] += __shfl_xor_sync(0xffffffffu, a[j], 2);
    }
    if (q == 0) {
        float dinv = rsqrtf((float)(gcn_degi[i] + 1));   // +1: self loop
        gcn_dinv[i] = dinv;
        gcn_bufA[2 * i]     = make_float4(a[0] * dinv, a[1] * dinv, a[2] * dinv, a[3] * dinv);
        gcn_bufA[2 * i + 1] = make_float4(a[4] * dinv, a[5] * dinv, 0.0f, 0.0f);
    }
}

// ---------------- fused CSR aggregation + epilogue + next-layer GEMM --------
// acc = g[i] + sum_{src->i} g[src]; h = relu(dinv*acc + b);
// out = APPLY_W ? (h @ W)*dinv : h*dinv
template <bool APPLY_W>
__global__ __launch_bounds__(256) void k_csr(const float4* __restrict__ vin,
                                             float4* __restrict__ vout,
                                             const float* __restrict__ b,
                                             const float* __restrict__ W, int N) {
    __shared__ float sW[48];
    __shared__ float sb[6];
    if (threadIdx.x < 48) {
        int k = threadIdx.x >> 3, j = threadIdx.x & 7;
        sW[threadIdx.x] = (APPLY_W && j < 6) ? W[k * 6 + j] : 0.0f;
    }
    if (threadIdx.x < 6) sb[threadIdx.x] = b[threadIdx.x];
    __syncthreads();
    int i = blockIdx.x * 256 + threadIdx.x;
    if (i >= N) return;

    float4 S0 = __ldg(&vin[2 * i]);
    float2 S1 = __ldg((const float2*)&vin[2 * i + 1]);
    float a0 = S0.x, a1 = S0.y, a2 = S0.z, a3 = S0.w, a4 = S1.x, a5 = S1.y;

    int e = gcn_off[i], end = gcn_off[i + 1];
#pragma unroll 1
    for (; e + 4 <= end; e += 4) {
        int s0 = gcn_csrc[e], s1 = gcn_csrc[e + 1], s2 = gcn_csrc[e + 2], s3 = gcn_csrc[e + 3];
        float4 p0 = __ldg(&vin[2 * s0]);
        float2 q0 = __ldg((const float2*)&vin[2 * s0 + 1]);
        float4 p1 = __ldg(&vin[2 * s1]);
        float2 q1 = __ldg((const float2*)&vin[2 * s1 + 1]);
        float4 p2 = __ldg(&vin[2 * s2]);
        float2 q2 = __ldg((const float2*)&vin[2 * s2 + 1]);
        float4 p3 = __ldg(&vin[2 * s3]);
        float2 q3 = __ldg((const float2*)&vin[2 * s3 + 1]);
        a0 += p0.x + p1.x + p2.x + p3.x;
        a1 += p0.y + p1.y + p2.y + p3.y;
        a2 += p0.z + p1.z + p2.z + p3.z;
        a3 += p0.w + p1.w + p2.w + p3.w;
        a4 += q0.x + q1.x + q2.x + q3.x;
        a5 += q0.y + q1.y + q2.y + q3.y;
    }
    for (; e < end; e++) {
        int s = gcn_csrc[e];
        float4 p = __ldg(&vin[2 * s]);
        float2 q = __ldg((const float2*)&vin[2 * s + 1]);
        a0 += p.x; a1 += p.y; a2 += p.z; a3 += p.w; a4 += q.x; a5 += q.y;
    }

    float dinv = gcn_dinv[i];
    float h[6];
    h[0] = fmaxf(dinv * a0 + sb[0], 0.0f);
    h[1] = fmaxf(dinv * a1 + sb[1], 0.0f);
    h[2] = fmaxf(dinv * a2 + sb[2], 0.0f);
    h[3] = fmaxf(dinv * a3 + sb[3], 0.0f);
    h[4] = fmaxf(dinv * a4 + sb[4], 0.0f);
    h[5] = fmaxf(dinv * a5 + sb[5], 0.0f);
    float o[6];
    if (APPLY_W) {
#pragma unroll
        for (int j = 0; j < 6; j++) {
            float s = 0.0f;
#pragma unroll
            for (int k = 0; k < 6; k++) s += h[k] * sW[k * 8 + j];
            o[j] = s * dinv;
        }
    } else {
#pragma unroll
        for (int j = 0; j < 6; j++) o[j] = h[j] * dinv;
    }
    vout[2 * i]     = make_float4(o[0], o[1], o[2], o[3]);
    vout[2 * i + 1] = make_float4(o[4], o[5], 0.0f, 0.0f);
}

// ---------------- final: CSR agg + (agg @ Wf + bf) relu + pooled sums -------
__global__ __launch_bounds__(256) void k_csr_final(const float4* __restrict__ vin,
                                                   const float* __restrict__ Wf,
                                                   const float* __restrict__ bf, int N) {
    __shared__ float sW[60];
    __shared__ float sb[10];
    __shared__ float sp[NG * NC];
    for (int t = threadIdx.x; t < NG * NC; t += 256) sp[t] = 0.0f;
    if (threadIdx.x < 60) sW[threadIdx.x] = Wf[threadIdx.x];
    if (threadIdx.x < 10) sb[threadIdx.x] = bf[threadIdx.x];
    __syncthreads();
    int i = blockIdx.x * 256 + threadIdx.x;
    if (i < N) {
        float4 S0 = __ldg(&vin[2 * i]);
        float2 S1 = __ldg((const float2*)&vin[2 * i + 1]);
        float a0 = S0.x, a1 = S0.y, a2 = S0.z, a3 = S0.w, a4 = S1.x, a5 = S1.y;
        int e = gcn_off[i], end = gcn_off[i + 1];
        for (; e < end; e++) {
            int s = gcn_csrc[e];
            float4 p = __ldg(&vin[2 * s]);
            float2 q = __ldg((const float2*)&vin[2 * s + 1]);
            a0 += p.x; a1 += p.y; a2 += p.z; a3 += p.w; a4 += q.x; a5 += q.y;
        }
        float dinv = gcn_dinv[i];
        float a[6] = { dinv * a0, dinv * a1, dinv * a2, dinv * a3, dinv * a4, dinv * a5 };
        int bg = gcn_batch[i];
#pragma unroll
        for (int c = 0; c < 10; c++) {
            float s = sb[c];
#pragma unroll
            for (int j = 0; j < 6; j++) s += a[j] * sW[j * 10 + c];
            s = fmaxf(s, 0.0f);
            atomicAdd(&sp[bg * 10 + c], s);
        }
    }
    __syncthreads();
    int first = blockIdx.x * 256;
    if (first >= N) return;
    int last = min(first + 255, N - 1);
    int bmin = gcn_batch[first], bmax = gcn_batch[last];   // batch sorted
    int cnt = (bmax - bmin + 1) * 10;
    for (int t = threadIdx.x; t < cnt; t += 256) {
        float v = sp[bmin * 10 + t];
        if (v != 0.0f) atomicAdd(&gcn_pool[bmin * 10 + t], v);
    }
}

// ---------------- mean + log_softmax ----------------
__global__ void k_out(float* __restrict__ out) {
    int g = threadIdx.x;
    if (g >= NG) return;
    float cnt = fmaxf(gcn_cnt[g], 1.0f);
    float p[10];
    float m = -1e30f;
#pragma unroll
    for (int c = 0; c < 10; c++) {
        p[c] = gcn_pool[g * 10 + c] / cnt;
        m = fmaxf(m, p[c]);
    }
    float s = 0.0f;
#pragma unroll
    for (int c = 0; c < 10; c++) s += expf(p[c] - m);
    float l = logf(s);
#pragma unroll
    for (int c = 0; c < 10; c++) out[g * 10 + c] = p[c] - m - l;
}

// ---------------- launch ----------------
extern "C" void kernel_launch(void* const* d_in, const int* in_sizes, int n_in,
                              void* d_out, int out_size) {
    const float* x     = (const float*)d_in[0];
    const void*  edge  = d_in[1];
    const void*  batch = d_in[2];
    const float* W1 = (const float*)d_in[3];
    const float* b1 = (const float*)d_in[4];
    const float* W2 = (const float*)d_in[5];
    const float* b2 = (const float*)d_in[6];
    const float* W3 = (const float*)d_in[7];
    const float* b3 = (const float*)d_in[8];
    const float* W4 = (const float*)d_in[9];
    const float* b4 = (const float*)d_in[10];
    const float* W5 = (const float*)d_in[11];
    const float* b5 = (const float*)d_in[12];
    const float* W6 = (const float*)d_in[13];
    const float* b6 = (const float*)d_in[14];
    const float* Wf = (const float*)d_in[15];
    const float* bf = (const float*)d_in[16];

    int N = in_sizes[0] / 128;
    int E = in_sizes[1] / 2;
    float* out = (float*)d_out;

    int nb_n  = (N + 255) / 256;
    int nb_e  = (E + 255) / 256;
    int nb_s  = (N + SCANB - 1) / SCANB;
    int nb_m  = (4 * N + 255) / 256;

    float4* A = gcn_bufA;  // __device__ symbols: addresses valid in device code only,
    float4* Bv = gcn_bufB; // but cudaGetSymbolAddress not needed — pass via kernel refs
    // NOTE: taking address of __device__ var on host is invalid; use kernels with
    // symbol access instead. We pass nullptr and let kernels reference globals? No —
    // instead get addresses via cudaGetSymbolAddress (allowed: no allocation).
    void* pA; void* pB;
    cudaGetSymbolAddress(&pA, gcn_bufA);
    cudaGetSymbolAddress(&pB, gcn_bufB);
    A = (float4*)pA; Bv = (float4*)pB;

    k_init<<<nb_n, 256>>>(N);
    k_detect<<<1, 32>>>(edge, N);
    k_hist<<<nb_e, 256>>>(edge, batch, N, E);
    k_scan1<<<nb_s, SCANB>>>(N);
    k_scan2<<<1, 128>>>(nb_s);
    k_scan3<<<nb_n, 256>>>(N, E);
    k_fill<<<nb_e, 256>>>(edge, E);

    k_mm1<<<nb_m, 256>>>(x, W1, N);                        // -> A (g1)
    k_csr<true><<<nb_n, 256>>>(A, Bv, b1, W2, N);          // -> B (g2)
    k_csr<true><<<nb_n, 256>>>(Bv, A, b2, W3, N);          // -> A (g3)
    k_csr<true><<<nb_n, 256>>>(A, Bv, b3, W4, N);          // -> B (g4)
    k_csr<true><<<nb_n, 256>>>(Bv, A, b4, W5, N);          // -> A (g5)
    k_csr<true><<<nb_n, 256>>>(A, Bv, b5, W6, N);          // -> B (g6)
    k_csr<false><<<nb_n, 256>>>(Bv, A, b6, nullptr, N);    // -> A (h6*dinv)
    k_csr_final<<<nb_n, 256>>>(A, Wf, bf, N);
    k_out<<<1, 64>>>(out);
}

// round 3
// speedup vs baseline: 1.3307x; 1.1394x over previous
#include <cuda_runtime.h>
#include <cuda_fp16.h>

#define NMAX 100000
#define EMAX 3200000
#define NG 64
#define NC 10
#define SCANB 1024

// ---------------- device scratch ----------------
__device__ int gcn_is64;
__device__ int gcn_degi[NMAX];          // in-degree (without self loop)
__device__ int gcn_off[NMAX + 1];       // CSR row offsets (by dst)
__device__ int gcn_cur[NMAX];           // fill cursors
__device__ int gcn_blocksum[128];
__device__ __align__(16) int gcn_csrc[EMAX];   // CSR column (src) indices
__device__ int gcn_batch[NMAX];
__device__ float gcn_dinv[NMAX];
__device__ __align__(16) uint4 gcn_bufA[NMAX];  // 6 halves packed per node (16B)
__device__ __align__(16) uint4 gcn_bufB[NMAX];
__device__ float gcn_pool[NG * NC];
__device__ float gcn_cnt[NG];

__device__ __forceinline__ uint4 pack6(float o0, float o1, float o2,
                                       float o3, float o4, float o5) {
    uint4 r;
    __half2 h01 = __floats2half2_rn(o0, o1);
    __half2 h23 = __floats2half2_rn(o2, o3);
    __half2 h45 = __floats2half2_rn(o4, o5);
    r.x = *(unsigned*)&h01;
    r.y = *(unsigned*)&h23;
    r.z = *(unsigned*)&h45;
    r.w = 0u;
    return r;
}

__device__ __forceinline__ void unpack_add(uint4 v, float& a0, float& a1, float& a2,
                                           float& a3, float& a4, float& a5) {
    float2 f0 = __half22float2(*(__half2*)&v.x);
    float2 f1 = __half22float2(*(__half2*)&v.y);
    float2 f2 = __half22float2(*(__half2*)&v.z);
    a0 += f0.x; a1 += f0.y; a2 += f1.x; a3 += f1.y; a4 += f2.x; a5 += f2.y;
}

// ---------------- init ----------------
__global__ __launch_bounds__(256) void k_init(int N) {
    int i = blockIdx.x * 256 + threadIdx.x;
    if (i < N) gcn_degi[i] = 0;
    if (i < NG) gcn_cnt[i] = 0.0f;
    if (i < NG * NC) gcn_pool[i] = 0.0f;
}

// ---------------- dtype detection: int32 vs int64 indices ----------------
__global__ void k_detect(const void* edge, int N) {
    const long long* p = (const long long*)edge;
    int bad = 0;
    for (int t = threadIdx.x; t < 128; t += 32) {
        long long v = p[t];
        if (v < 0 || v >= (long long)N) bad = 1;
    }
    bad = __any_sync(0xffffffffu, bad);
    if (threadIdx.x == 0) gcn_is64 = bad ? 0 : 1;
}

// ---------------- degree histogram + batch counts ----------------
__global__ __launch_bounds__(256) void k_hist(const void* edge, const void* batchp,
                                              int N, int E) {
    int i = blockIdx.x * 256 + threadIdx.x;
    int is64 = gcn_is64;
    if (i < E) {
        int d = is64 ? (int)((const long long*)edge)[(size_t)E + i]
                     : ((const int*)edge)[(size_t)E + i];
        atomicAdd(&gcn_degi[d], 1);
    }
    if (i < N) {
        int b = is64 ? (int)((const long long*)batchp)[i] : ((const int*)batchp)[i];
        gcn_batch[i] = b;
        atomicAdd(&gcn_cnt[b], 1.0f);
    }
}

// ---------------- 3-phase exclusive scan of degi -> off ----------------
__global__ __launch_bounds__(SCANB) void k_scan1(int N) {
    __shared__ int s[SCANB];
    int t = threadIdx.x;
    int i = blockIdx.x * SCANB + t;
    int v = (i < N) ? gcn_degi[i] : 0;
    s[t] = v;
    __syncthreads();
    for (int d = 1; d < SCANB; d <<= 1) {
        int x = (t >= d) ? s[t - d] : 0;
        __syncthreads();
        s[t] += x;
        __syncthreads();
    }
    if (i < N) gcn_off[i] = s[t] - v;   // exclusive (local)
    if (t == SCANB - 1) gcn_blocksum[blockIdx.x] = s[t];
}

__global__ void k_scan2(int nblk) {
    __shared__ int s[128];
    int t = threadIdx.x;
    int v = (t < nblk) ? gcn_blocksum[t] : 0;
    s[t] = v;
    __syncthreads();
    for (int d = 1; d < 128; d <<= 1) {
        int x = (t >= d) ? s[t - d] : 0;
        __syncthreads();
        s[t] += x;
        __syncthreads();
    }
    if (t < nblk) gcn_blocksum[t] = s[t] - v;  // exclusive block bases
}

__global__ __launch_bounds__(256) void k_scan3(int N, int E) {
    int i = blockIdx.x * 256 + threadIdx.x;
    if (i < N) {
        int o = gcn_off[i] + gcn_blocksum[i >> 10];
        gcn_off[i] = o;
        gcn_cur[i] = o;
    }
    if (i == 0) gcn_off[N] = E;
}

// ---------------- CSR fill (counting-sort edges by dst) ----------------
__global__ __launch_bounds__(256) void k_fill(const void* edge, int E) {
    int i = blockIdx.x * 256 + threadIdx.x;
    if (i >= E) return;
    int is64 = gcn_is64;
    int s, d;
    if (is64) {
        s = (int)((const long long*)edge)[i];
        d = (int)((const long long*)edge)[(size_t)E + i];
    } else {
        s = ((const int*)edge)[i];
        d = ((const int*)edge)[(size_t)E + i];
    }
    int pos = atomicAdd(&gcn_cur[d], 1);
    gcn_csrc[pos] = s;
}

// ---------------- layer-1 transform: bufA = fp16( (x @ W1) * dinv ) ----------
// 4 threads per row, shfl-combined.
__global__ __launch_bounds__(256) void k_mm1(const float* __restrict__ x,
                                             const float* __restrict__ W, int N) {
    __shared__ float sW[128 * 8];
    for (int t = threadIdx.x; t < 1024; t += 256) {
        int k = t >> 3, j = t & 7;
        sW[t] = (j < 6) ? W[k * 6 + j] : 0.0f;
    }
    __syncthreads();
    int g = blockIdx.x * 256 + threadIdx.x;
    int i = g >> 2;
    int q = g & 3;
    if (i >= N) return;
    const float4* xr = (const float4*)(x + (size_t)i * 128) + q * 8;
    float a[6];
#pragma unroll
    for (int j = 0; j < 6; j++) a[j] = 0.0f;
#pragma unroll
    for (int k4 = 0; k4 < 8; k4++) {
        float4 xv = xr[k4];
        const float* wp = &sW[(q * 8 + k4) * 32];
#pragma unroll
        for (int j = 0; j < 6; j++) {
            a[j] += xv.x * wp[j] + xv.y * wp[8 + j] + xv.z * wp[16 + j] + xv.w * wp[24 + j];
        }
    }
#pragma unroll
    for (int j = 0; j < 6; j++) {
        a[j] += __shfl_xor_sync(0xffffffffu, a[j], 1);
        a[j] += __shfl_xor_sync(0xffffffffu, a[j], 2);
    }
    if (q == 0) {
        float dinv = rsqrtf((float)(gcn_degi[i] + 1));   // +1: self loop
        gcn_dinv[i] = dinv;
        gcn_bufA[i] = pack6(a[0] * dinv, a[1] * dinv, a[2] * dinv,
                            a[3] * dinv, a[4] * dinv, a[5] * dinv);
    }
}

// ---------------- fused CSR aggregation + epilogue + next-layer GEMM --------
// acc = g[i] + sum_{src->i} g[src]; h = relu(dinv*acc + b);
// out = APPLY_W ? (h @ W)*dinv : h*dinv   (fp16 packed)
template <bool APPLY_W>
__global__ __launch_bounds__(256) void k_csr(const uint4* __restrict__ vin,
                                             uint4* __restrict__ vout,
                                             const float* __restrict__ b,
                                             const float* __restrict__ W, int N) {
    __shared__ float sW[48];
    __shared__ float sb[6];
    if (threadIdx.x < 48) {
        int k = threadIdx.x >> 3, j = threadIdx.x & 7;
        sW[threadIdx.x] = (APPLY_W && j < 6) ? W[k * 6 + j] : 0.0f;
    }
    if (threadIdx.x < 6) sb[threadIdx.x] = b[threadIdx.x];
    __syncthreads();
    int i = blockIdx.x * 256 + threadIdx.x;
    if (i >= N) return;

    float a0, a1, a2, a3, a4, a5;
    a0 = a1 = a2 = a3 = a4 = a5 = 0.0f;
    unpack_add(__ldg(&vin[i]), a0, a1, a2, a3, a4, a5);   // self loop

    int e = gcn_off[i], end = gcn_off[i + 1];
    // head to 16B alignment of index stream
    while (e < end && (e & 3)) {
        unpack_add(__ldg(&vin[gcn_csrc[e]]), a0, a1, a2, a3, a4, a5);
        e++;
    }
#pragma unroll 1
    for (; e + 4 <= end; e += 4) {
        int4 s4 = *(const int4*)&gcn_csrc[e];
        uint4 v0 = __ldg(&vin[s4.x]);
        uint4 v1 = __ldg(&vin[s4.y]);
        uint4 v2 = __ldg(&vin[s4.z]);
        uint4 v3 = __ldg(&vin[s4.w]);
        unpack_add(v0, a0, a1, a2, a3, a4, a5);
        unpack_add(v1, a0, a1, a2, a3, a4, a5);
        unpack_add(v2, a0, a1, a2, a3, a4, a5);
        unpack_add(v3, a0, a1, a2, a3, a4, a5);
    }
    for (; e < end; e++) {
        unpack_add(__ldg(&vin[gcn_csrc[e]]), a0, a1, a2, a3, a4, a5);
    }

    float dinv = gcn_dinv[i];
    float h[6];
    h[0] = fmaxf(dinv * a0 + sb[0], 0.0f);
    h[1] = fmaxf(dinv * a1 + sb[1], 0.0f);
    h[2] = fmaxf(dinv * a2 + sb[2], 0.0f);
    h[3] = fmaxf(dinv * a3 + sb[3], 0.0f);
    h[4] = fmaxf(dinv * a4 + sb[4], 0.0f);
    h[5] = fmaxf(dinv * a5 + sb[5], 0.0f);
    float o[6];
    if (APPLY_W) {
#pragma unroll
        for (int j = 0; j < 6; j++) {
            float s = 0.0f;
#pragma unroll
            for (int k = 0; k < 6; k++) s += h[k] * sW[k * 8 + j];
            o[j] = s * dinv;
        }
    } else {
#pragma unroll
        for (int j = 0; j < 6; j++) o[j] = h[j] * dinv;
    }
    vout[i] = pack6(o[0], o[1], o[2], o[3], o[4], o[5]);
}

// ---------------- final: CSR agg + (agg @ Wf + bf) relu + pooled sums -------
__global__ __launch_bounds__(256) void k_csr_final(const uint4* __restrict__ vin,
                                                   const float* __restrict__ Wf,
                                                   const float* __restrict__ bf, int N) {
    __shared__ float sW[60];
    __shared__ float sb[10];
    __shared__ float sp[NG * NC];
    for (int t = threadIdx.x; t < NG * NC; t += 256) sp[t] = 0.0f;
    if (threadIdx.x < 60) sW[threadIdx.x] = Wf[threadIdx.x];
    if (threadIdx.x < 10) sb[threadIdx.x] = bf[threadIdx.x];
    __syncthreads();
    int i = blockIdx.x * 256 + threadIdx.x;
    if (i < N) {
        float a0, a1, a2, a3, a4, a5;
        a0 = a1 = a2 = a3 = a4 = a5 = 0.0f;
        unpack_add(__ldg(&vin[i]), a0, a1, a2, a3, a4, a5);
        int e = gcn_off[i], end = gcn_off[i + 1];
        while (e < end && (e & 3)) {
            unpack_add(__ldg(&vin[gcn_csrc[e]]), a0, a1, a2, a3, a4, a5);
            e++;
        }
#pragma unroll 1
        for (; e + 4 <= end; e += 4) {
            int4 s4 = *(const int4*)&gcn_csrc[e];
            uint4 v0 = __ldg(&vin[s4.x]);
            uint4 v1 = __ldg(&vin[s4.y]);
            uint4 v2 = __ldg(&vin[s4.z]);
            uint4 v3 = __ldg(&vin[s4.w]);
            unpack_add(v0, a0, a1, a2, a3, a4, a5);
            unpack_add(v1, a0, a1, a2, a3, a4, a5);
            unpack_add(v2, a0, a1, a2, a3, a4, a5);
            unpack_add(v3, a0, a1, a2, a3, a4, a5);
        }
        for (; e < end; e++) {
            unpack_add(__ldg(&vin[gcn_csrc[e]]), a0, a1, a2, a3, a4, a5);
        }
        float dinv = gcn_dinv[i];
        float a[6] = { dinv * a0, dinv * a1, dinv * a2, dinv * a3, dinv * a4, dinv * a5 };
        int bg = gcn_batch[i];
#pragma unroll
        for (int c = 0; c < 10; c++) {
            float s = sb[c];
#pragma unroll
            for (int j = 0; j < 6; j++) s += a[j] * sW[j * 10 + c];
            s = fmaxf(s, 0.0f);
            atomicAdd(&sp[bg * 10 + c], s);
        }
    }
    __syncthreads();
    int first = blockIdx.x * 256;
    if (first >= N) return;
    int last = min(first + 255, N - 1);
    int bmin = gcn_batch[first], bmax = gcn_batch[last];   // batch sorted
    int cnt = (bmax - bmin + 1) * 10;
    for (int t = threadIdx.x; t < cnt; t += 256) {
        float v = sp[bmin * 10 + t];
        if (v != 0.0f) atomicAdd(&gcn_pool[bmin * 10 + t], v);
    }
}

// ---------------- mean + log_softmax ----------------
__global__ void k_out(float* __restrict__ out) {
    int g = threadIdx.x;
    if (g >= NG) return;
    float cnt = fmaxf(gcn_cnt[g], 1.0f);
    float p[10];
    float m = -1e30f;
#pragma unroll
    for (int c = 0; c < 10; c++) {
        p[c] = gcn_pool[g * 10 + c] / cnt;
        m = fmaxf(m, p[c]);
    }
    float s = 0.0f;
#pragma unroll
    for (int c = 0; c < 10; c++) s += expf(p[c] - m);
    float l = logf(s);
#pragma unroll
    for (int c = 0; c < 10; c++) out[g * 10 + c] = p[c] - m - l;
}

// ---------------- launch ----------------
extern "C" void kernel_launch(void* const* d_in, const int* in_sizes, int n_in,
                              void* d_out, int out_size) {
    const float* x     = (const float*)d_in[0];
    const void*  edge  = d_in[1];
    const void*  batch = d_in[2];
    const float* W1 = (const float*)d_in[3];
    const float* b1 = (const float*)d_in[4];
    const float* W2 = (const float*)d_in[5];
    const float* b2 = (const float*)d_in[6];
    const float* W3 = (const float*)d_in[7];
    const float* b3 = (const float*)d_in[8];
    const float* W4 = (const float*)d_in[9];
    const float* b4 = (const float*)d_in[10];
    const float* W5 = (const float*)d_in[11];
    const float* b5 = (const float*)d_in[12];
    const float* W6 = (const float*)d_in[13];
    const float* b6 = (const float*)d_in[14];
    const float* Wf = (const float*)d_in[15];
    const float* bf = (const float*)d_in[16];

    int N = in_sizes[0] / 128;
    int E = in_sizes[1] / 2;
    float* out = (float*)d_out;

    int nb_n  = (N + 255) / 256;
    int nb_e  = (E + 255) / 256;
    int nb_s  = (N + SCANB - 1) / SCANB;
    int nb_m  = (4 * N + 255) / 256;

    void* pA; void* pB;
    cudaGetSymbolAddress(&pA, gcn_bufA);
    cudaGetSymbolAddress(&pB, gcn_bufB);
    uint4* A  = (uint4*)pA;
    uint4* Bv = (uint4*)pB;

    k_init<<<nb_n, 256>>>(N);
    k_detect<<<1, 32>>>(edge, N);
    k_hist<<<nb_e, 256>>>(edge, batch, N, E);
    k_scan1<<<nb_s, SCANB>>>(N);
    k_scan2<<<1, 128>>>(nb_s);
    k_scan3<<<nb_n, 256>>>(N, E);
    k_fill<<<nb_e, 256>>>(edge, E);

    k_mm1<<<nb_m, 256>>>(x, W1, N);                        // -> A (g1)
    k_csr<true><<<nb_n, 256>>>(A, Bv, b1, W2, N);          // -> B (g2)
    k_csr<true><<<nb_n, 256>>>(Bv, A, b2, W3, N);          // -> A (g3)
    k_csr<true><<<nb_n, 256>>>(A, Bv, b3, W4, N);          // -> B (g4)
    k_csr<true><<<nb_n, 256>>>(Bv, A, b4, W5, N);          // -> A (g5)
    k_csr<true><<<nb_n, 256>>>(A, Bv, b5, W6, N);          // -> B (g6)
    k_csr<false><<<nb_n, 256>>>(Bv, A, b6, nullptr, N);    // -> A (h6*dinv)
    k_csr_final<<<nb_n, 256>>>(A, Wf, bf, N);
    k_out<<<1, 64>>>(out);
}

// round 4
// speedup vs baseline: 1.4010x; 1.0529x over previous
#include <cuda_runtime.h>
#include <cuda_fp16.h>

#define NMAX 100000
#define EMAX 3200000
#define NG 64
#define NC 10
#define SCANB 1024

// ---------------- device scratch ----------------
__device__ int gcn_is64;
__device__ int gcn_degi[NMAX];          // in-degree (without self loop)
__device__ int gcn_off[NMAX + 1];       // CSR row offsets (by dst)
__device__ int gcn_cur[NMAX];           // fill cursors
__device__ int gcn_blocksum[128];
__device__ __align__(16) int gcn_csrc[EMAX];   // CSR column (src) indices
__device__ int gcn_batch[NMAX];
__device__ float gcn_dinv[NMAX];
__device__ __align__(16) uint4 gcn_bufA[NMAX];  // 6 halves packed per node (16B)
__device__ __align__(16) uint4 gcn_bufB[NMAX];
__device__ float gcn_pool[NG * NC];
__device__ float gcn_cnt[NG];

__device__ __forceinline__ uint4 pack6(const float* o) {
    uint4 r;
    __half2 h01 = __floats2half2_rn(o[0], o[1]);
    __half2 h23 = __floats2half2_rn(o[2], o[3]);
    __half2 h45 = __floats2half2_rn(o[4], o[5]);
    r.x = *(unsigned*)&h01;
    r.y = *(unsigned*)&h23;
    r.z = *(unsigned*)&h45;
    r.w = 0u;
    return r;
}

__device__ __forceinline__ void unpack_add(uint4 v, float* a) {
    float2 f0 = __half22float2(*(__half2*)&v.x);
    float2 f1 = __half22float2(*(__half2*)&v.y);
    float2 f2 = __half22float2(*(__half2*)&v.z);
    a[0] += f0.x; a[1] += f0.y; a[2] += f1.x; a[3] += f1.y; a[4] += f2.x; a[5] += f2.y;
}

// ---------------- init ----------------
__global__ __launch_bounds__(256) void k_init(int N) {
    int i = blockIdx.x * 256 + threadIdx.x;
    if (i < N) gcn_degi[i] = 0;
    if (i < NG) gcn_cnt[i] = 0.0f;
    if (i < NG * NC) gcn_pool[i] = 0.0f;
}

// ---------------- dtype detection: int32 vs int64 indices ----------------
__global__ void k_detect(const void* edge, int N) {
    const long long* p = (const long long*)edge;
    int bad = 0;
    for (int t = threadIdx.x; t < 128; t += 32) {
        long long v = p[t];
        if (v < 0 || v >= (long long)N) bad = 1;
    }
    bad = __any_sync(0xffffffffu, bad);
    if (threadIdx.x == 0) gcn_is64 = bad ? 0 : 1;
}

// ---------------- degree histogram + batch counts ----------------
__global__ __launch_bounds__(256) void k_hist(const void* edge, const void* batchp,
                                              int N, int E) {
    int i = blockIdx.x * 256 + threadIdx.x;
    int is64 = gcn_is64;
    if (i < E) {
        int d = is64 ? (int)((const long long*)edge)[(size_t)E + i]
                     : ((const int*)edge)[(size_t)E + i];
        atomicAdd(&gcn_degi[d], 1);
    }
    if (i < N) {
        int b = is64 ? (int)((const long long*)batchp)[i] : ((const int*)batchp)[i];
        gcn_batch[i] = b;
        atomicAdd(&gcn_cnt[b], 1.0f);
    }
}

// ---------------- 3-phase exclusive scan of degi -> off ----------------
__global__ __launch_bounds__(SCANB) void k_scan1(int N) {
    __shared__ int s[SCANB];
    int t = threadIdx.x;
    int i = blockIdx.x * SCANB + t;
    int v = (i < N) ? gcn_degi[i] : 0;
    s[t] = v;
    __syncthreads();
    for (int d = 1; d < SCANB; d <<= 1) {
        int x = (t >= d) ? s[t - d] : 0;
        __syncthreads();
        s[t] += x;
        __syncthreads();
    }
    if (i < N) gcn_off[i] = s[t] - v;   // exclusive (local)
    if (t == SCANB - 1) gcn_blocksum[blockIdx.x] = s[t];
}

__global__ void k_scan2(int nblk) {
    __shared__ int s[128];
    int t = threadIdx.x;
    int v = (t < nblk) ? gcn_blocksum[t] : 0;
    s[t] = v;
    __syncthreads();
    for (int d = 1; d < 128; d <<= 1) {
        int x = (t >= d) ? s[t - d] : 0;
        __syncthreads();
        s[t] += x;
        __syncthreads();
    }
    if (t < nblk) gcn_blocksum[t] = s[t] - v;  // exclusive block bases
}

__global__ __launch_bounds__(256) void k_scan3(int N, int E) {
    int i = blockIdx.x * 256 + threadIdx.x;
    if (i < N) {
        int o = gcn_off[i] + gcn_blocksum[i >> 10];
        gcn_off[i] = o;
        gcn_cur[i] = o;
    }
    if (i == 0) gcn_off[N] = E;
}

// ---------------- CSR fill (counting-sort edges by dst) ----------------
__global__ __launch_bounds__(256) void k_fill(const void* edge, int E) {
    int i = blockIdx.x * 256 + threadIdx.x;
    if (i >= E) return;
    int is64 = gcn_is64;
    int s, d;
    if (is64) {
        s = (int)((const long long*)edge)[i];
        d = (int)((const long long*)edge)[(size_t)E + i];
    } else {
        s = ((const int*)edge)[i];
        d = ((const int*)edge)[(size_t)E + i];
    }
    int pos = atomicAdd(&gcn_cur[d], 1);
    gcn_csrc[pos] = s;
}

// ---------------- layer-1 transform: bufA = fp16( (x @ W1) * dinv ) ----------
__global__ __launch_bounds__(256) void k_mm1(const float* __restrict__ x,
                                             const float* __restrict__ W, int N) {
    __shared__ float sW[128 * 8];
    for (int t = threadIdx.x; t < 1024; t += 256) {
        int k = t >> 3, j = t & 7;
        sW[t] = (j < 6) ? W[k * 6 + j] : 0.0f;
    }
    __syncthreads();
    int g = blockIdx.x * 256 + threadIdx.x;
    int i = g >> 2;
    int q = g & 3;
    if (i >= N) return;
    const float4* xr = (const float4*)(x + (size_t)i * 128) + q * 8;
    float a[6];
#pragma unroll
    for (int j = 0; j < 6; j++) a[j] = 0.0f;
#pragma unroll
    for (int k4 = 0; k4 < 8; k4++) {
        float4 xv = xr[k4];
        const float* wp = &sW[(q * 8 + k4) * 32];
#pragma unroll
        for (int j = 0; j < 6; j++) {
            a[j] += xv.x * wp[j] + xv.y * wp[8 + j] + xv.z * wp[16 + j] + xv.w * wp[24 + j];
        }
    }
#pragma unroll
    for (int j = 0; j < 6; j++) {
        a[j] += __shfl_xor_sync(0xffffffffu, a[j], 1);
        a[j] += __shfl_xor_sync(0xffffffffu, a[j], 2);
    }
    if (q == 0) {
        float dinv = rsqrtf((float)(gcn_degi[i] + 1));   // +1: self loop
        gcn_dinv[i] = dinv;
        float o[6] = { a[0] * dinv, a[1] * dinv, a[2] * dinv,
                       a[3] * dinv, a[4] * dinv, a[5] * dinv };
        gcn_bufA[i] = pack6(o);
    }
}

// ---------------- fused CSR aggregation (4 threads/node) + epilogue + GEMM --
// acc = g[i] + sum_{src->i} g[src]; h = relu(dinv*acc + b);
// out = APPLY_W ? (h @ W)*dinv : h*dinv   (fp16 packed)
template <bool APPLY_W>
__global__ __launch_bounds__(256) void k_csr(const uint4* __restrict__ vin,
                                             uint4* __restrict__ vout,
                                             const float* __restrict__ b,
                                             const float* __restrict__ W, int N) {
    __shared__ float sW[48];
    __shared__ float sb[6];
    if (threadIdx.x < 48) {
        int k = threadIdx.x >> 3, j = threadIdx.x & 7;
        sW[threadIdx.x] = (APPLY_W && j < 6) ? W[k * 6 + j] : 0.0f;
    }
    if (threadIdx.x < 6) sb[threadIdx.x] = b[threadIdx.x];
    __syncthreads();
    int g = blockIdx.x * 256 + threadIdx.x;
    int i = g >> 2;
    int q = g & 3;
    bool valid = (i < N);
    int base = 0, end = 0;
    if (valid) { base = gcn_off[i]; end = gcn_off[i + 1]; }

    float a[6] = {0, 0, 0, 0, 0, 0};
    int e = base + q;
    // 2-way unrolled strided walk: two independent gathers in flight per iter
#pragma unroll 1
    for (; e + 4 < end; e += 8) {
        int s0 = gcn_csrc[e];
        int s1 = gcn_csrc[e + 4];
        uint4 v0 = __ldg(&vin[s0]);
        uint4 v1 = __ldg(&vin[s1]);
        unpack_add(v0, a);
        unpack_add(v1, a);
    }
    if (e < end) unpack_add(__ldg(&vin[gcn_csrc[e]]), a);

    // combine quarter-warp partials
#pragma unroll
    for (int j = 0; j < 6; j++) {
        a[j] += __shfl_xor_sync(0xffffffffu, a[j], 1);
        a[j] += __shfl_xor_sync(0xffffffffu, a[j], 2);
    }
    if (!valid || q != 0) return;

    unpack_add(__ldg(&vin[i]), a);       // self loop
    float dinv = gcn_dinv[i];
    float h[6];
#pragma unroll
    for (int j = 0; j < 6; j++) h[j] = fmaxf(dinv * a[j] + sb[j], 0.0f);
    float o[6];
    if (APPLY_W) {
#pragma unroll
        for (int j = 0; j < 6; j++) {
            float s = 0.0f;
#pragma unroll
            for (int k = 0; k < 6; k++) s += h[k] * sW[k * 8 + j];
            o[j] = s * dinv;
        }
    } else {
#pragma unroll
        for (int j = 0; j < 6; j++) o[j] = h[j] * dinv;
    }
    vout[i] = pack6(o);
}

// ---------------- final: CSR agg (4t/node) + (agg @ Wf + bf) relu + pool ----
__global__ __launch_bounds__(256) void k_csr_final(const uint4* __restrict__ vin,
                                                   const float* __restrict__ Wf,
                                                   const float* __restrict__ bf, int N) {
    __shared__ float sW[60];
    __shared__ float sb[10];
    __shared__ float sp[NG * NC];
    for (int t = threadIdx.x; t < NG * NC; t += 256) sp[t] = 0.0f;
    if (threadIdx.x < 60) sW[threadIdx.x] = Wf[threadIdx.x];
    if (threadIdx.x < 10) sb[threadIdx.x] = bf[threadIdx.x];
    __syncthreads();
    int g = blockIdx.x * 256 + threadIdx.x;
    int i = g >> 2;
    int q = g & 3;
    bool valid = (i < N);
    int base = 0, end = 0;
    if (valid) { base = gcn_off[i]; end = gcn_off[i + 1]; }

    float a[6] = {0, 0, 0, 0, 0, 0};
    int e = base + q;
#pragma unroll 1
    for (; e + 4 < end; e += 8) {
        int s0 = gcn_csrc[e];
        int s1 = gcn_csrc[e + 4];
        uint4 v0 = __ldg(&vin[s0]);
        uint4 v1 = __ldg(&vin[s1]);
        unpack_add(v0, a);
        unpack_add(v1, a);
    }
    if (e < end) unpack_add(__ldg(&vin[gcn_csrc[e]]), a);
#pragma unroll
    for (int j = 0; j < 6; j++) {
        a[j] += __shfl_xor_sync(0xffffffffu, a[j], 1);
        a[j] += __shfl_xor_sync(0xffffffffu, a[j], 2);
    }
    if (valid && q == 0) {
        unpack_add(__ldg(&vin[i]), a);
        float dinv = gcn_dinv[i];
#pragma unroll
        for (int j = 0; j < 6; j++) a[j] *= dinv;
        int bg = gcn_batch[i];
#pragma unroll
        for (int c = 0; c < 10; c++) {
            float s = sb[c];
#pragma unroll
            for (int j = 0; j < 6; j++) s += a[j] * sW[j * 10 + c];
            s = fmaxf(s, 0.0f);
            atomicAdd(&sp[bg * 10 + c], s);
        }
    }
    __syncthreads();
    int first = blockIdx.x * 64;           // 64 nodes per block (4 threads each)
    if (first >= N) return;
    int last = min(first + 63, N - 1);
    int bmin = gcn_batch[first], bmax = gcn_batch[last];   // batch sorted
    int cnt = (bmax - bmin + 1) * 10;
    for (int t = threadIdx.x; t < cnt; t += 256) {
        float v = sp[bmin * 10 + t];
        if (v != 0.0f) atomicAdd(&gcn_pool[bmin * 10 + t], v);
    }
}

// ---------------- mean + log_softmax ----------------
__global__ void k_out(float* __restrict__ out) {
    int g = threadIdx.x;
    if (g >= NG) return;
    float cnt = fmaxf(gcn_cnt[g], 1.0f);
    float p[10];
    float m = -1e30f;
#pragma unroll
    for (int c = 0; c < 10; c++) {
        p[c] = gcn_pool[g * 10 + c] / cnt;
        m = fmaxf(m, p[c]);
    }
    float s = 0.0f;
#pragma unroll
    for (int c = 0; c < 10; c++) s += expf(p[c] - m);
    float l = logf(s);
#pragma unroll
    for (int c = 0; c < 10; c++) out[g * 10 + c] = p[c] - m - l;
}

// ---------------- launch ----------------
extern "C" void kernel_launch(void* const* d_in, const int* in_sizes, int n_in,
                              void* d_out, int out_size) {
    const float* x     = (const float*)d_in[0];
    const void*  edge  = d_in[1];
    const void*  batch = d_in[2];
    const float* W1 = (const float*)d_in[3];
    const float* b1 = (const float*)d_in[4];
    const float* W2 = (const float*)d_in[5];
    const float* b2 = (const float*)d_in[6];
    const float* W3 = (const float*)d_in[7];
    const float* b3 = (const float*)d_in[8];
    const float* W4 = (const float*)d_in[9];
    const float* b4 = (const float*)d_in[10];
    const float* W5 = (const float*)d_in[11];
    const float* b5 = (const float*)d_in[12];
    const float* W6 = (const float*)d_in[13];
    const float* b6 = (const float*)d_in[14];
    const float* Wf = (const float*)d_in[15];
    const float* bf = (const float*)d_in[16];

    int N = in_sizes[0] / 128;
    int E = in_sizes[1] / 2;
    float* out = (float*)d_out;

    int nb_n  = (N + 255) / 256;
    int nb_e  = (E + 255) / 256;
    int nb_s  = (N + SCANB - 1) / SCANB;
    int nb_m  = (4 * N + 255) / 256;   // 4 threads per node

    void* pA; void* pB;
    cudaGetSymbolAddress(&pA, gcn_bufA);
    cudaGetSymbolAddress(&pB, gcn_bufB);
    uint4* A  = (uint4*)pA;
    uint4* Bv = (uint4*)pB;

    k_init<<<nb_n, 256>>>(N);
    k_detect<<<1, 32>>>(edge, N);
    k_hist<<<nb_e, 256>>>(edge, batch, N, E);
    k_scan1<<<nb_s, SCANB>>>(N);
    k_scan2<<<1, 128>>>(nb_s);
    k_scan3<<<nb_n, 256>>>(N, E);
    k_fill<<<nb_e, 256>>>(edge, E);

    k_mm1<<<nb_m, 256>>>(x, W1, N);                        // -> A (g1)
    k_csr<true><<<nb_m, 256>>>(A, Bv, b1, W2, N);          // -> B (g2)
    k_csr<true><<<nb_m, 256>>>(Bv, A, b2, W3, N);          // -> A (g3)
    k_csr<true><<<nb_m, 256>>>(A, Bv, b3, W4, N);          // -> B (g4)
    k_csr<true><<<nb_m, 256>>>(Bv, A, b4, W5, N);          // -> A (g5)
    k_csr<true><<<nb_m, 256>>>(A, Bv, b5, W6, N);          // -> B (g6)
    k_csr<false><<<nb_m, 256>>>(Bv, A, b6, nullptr, N);    // -> A (h6*dinv)
    k_csr_final<<<nb_m, 256>>>(A, Wf, bf, N);
    k_out<<<1, 64>>>(out);
}